// round 15
// baseline (speedup 1.0000x reference)
#include <cuda_runtime.h>
#include <cuda_fp16.h>
#include <cstdint>

#define N_NODES 100000
#define N_EDGES 3200000
#define F_IN 128
#define NOUT 32

#define SCAN_BLOCK 1024
#define SCAN_NBLK ((N_NODES + SCAN_BLOCK - 1) / SCAN_BLOCK)   // 98

// B-tile stride: pattern (tg*S + j*8 + g) needs S % 32 == 8 -> 136
// H-tile stride: pattern (g*S + tg)      needs S % 32 == 4 -> 36
#define BSTRIDE 136
#define HSTRIDE 36
#define PSTRIDE 34

// Scratch (allocation-free: __device__ globals)
__device__ __half g_hc16[N_NODES * NOUT];   // conv branch, gather source (fp16)
__device__ __half g_h16[N_NODES * NOUT];    // layer output h (fp16 handoff)
__device__ float  g_dense[N_NODES * NOUT];
__device__ int    g_deg[N_NODES];
__device__ int    g_rowstart[N_NODES];
__device__ int    g_cursor[N_NODES];        // after fill: row END
__device__ int    g_counter[1];
__device__ int    g_csr[N_EDGES];

__device__ __forceinline__ uint32_t f2tf32(float f) {
    uint32_t r;
    asm("cvt.rna.tf32.f32 %0, %1;" : "=r"(r) : "f"(f));
    return r;
}

__device__ __forceinline__ void mma_tf32(float& d0, float& d1, float& d2, float& d3,
                                         uint32_t a0, uint32_t a1, uint32_t a2,
                                         uint32_t a3, uint32_t b0, uint32_t b1) {
    asm volatile(
        "mma.sync.aligned.m16n8k8.row.col.f32.tf32.tf32.f32 "
        "{%0,%1,%2,%3}, {%4,%5,%6,%7}, {%8,%9}, {%0,%1,%2,%3};"
        : "+f"(d0), "+f"(d1), "+f"(d2), "+f"(d3)
        : "r"(a0), "r"(a1), "r"(a2), "r"(a3), "r"(b0), "r"(b1));
}

// ===========================================================================
// CSR build: memset(deg,counter) -> hist(int4) -> scanA -> fill
// ===========================================================================
__global__ void k_hist(const int* __restrict__ dst, int* __restrict__ deg)
{
    int t = blockIdx.x * blockDim.x + threadIdx.x;
    int e4 = t * 4;
    if (e4 + 4 <= N_EDGES) {
        int4 d = *reinterpret_cast<const int4*>(dst + e4);
        atomicAdd(&deg[d.x], 1);
        atomicAdd(&deg[d.y], 1);
        atomicAdd(&deg[d.z], 1);
        atomicAdd(&deg[d.w], 1);
    } else {
        for (int e = e4; e < N_EDGES; e++)
            atomicAdd(&deg[dst[e]], 1);
    }
}

// One-shot scan (bases non-monotonic; per-node ranges disjoint — sufficient).
__global__ void k_scanA(const int* __restrict__ deg, int* __restrict__ rowstart,
                        int* __restrict__ cursor, int* __restrict__ counter)
{
    __shared__ int sh[SCAN_BLOCK];
    __shared__ int base_sh;
    int i = blockIdx.x * SCAN_BLOCK + threadIdx.x;
    int v = (i < N_NODES) ? deg[i] : 0;
    sh[threadIdx.x] = v;
    __syncthreads();
    for (int off = 1; off < SCAN_BLOCK; off <<= 1) {
        int t = (threadIdx.x >= off) ? sh[threadIdx.x - off] : 0;
        __syncthreads();
        sh[threadIdx.x] += t;
        __syncthreads();
    }
    if (threadIdx.x == SCAN_BLOCK - 1)
        base_sh = atomicAdd(counter, sh[SCAN_BLOCK - 1]);
    __syncthreads();
    if (i < N_NODES) {
        int r = base_sh + sh[threadIdx.x] - v;
        rowstart[i] = r;
        cursor[i] = r;
    }
}

__global__ void k_fill(const int* __restrict__ src, const int* __restrict__ dst,
                       int* __restrict__ cursor, int* __restrict__ csr)
{
    int e = blockIdx.x * blockDim.x + threadIdx.x;
    if (e < N_EDGES) {
        int pos = atomicAdd(&cursor[dst[e]], 1);
        csr[pos] = src[e];
    }
}

// ===========================================================================
// Gather core v2: warp per node. One coalesced csr load covers the first 32
// edges; ids distributed via shfl so all hc-load batches issue independently.
// 4 lanes/edge, lane = 16B quarter of the 64B hc row. fp32 accumulate.
// ===========================================================================
__device__ __forceinline__ void gacc(float* acc, uint4 v)
{
    float2 f0 = __half22float2(*reinterpret_cast<__half2*>(&v.x));
    float2 f1 = __half22float2(*reinterpret_cast<__half2*>(&v.y));
    float2 f2 = __half22float2(*reinterpret_cast<__half2*>(&v.z));
    float2 f3 = __half22float2(*reinterpret_cast<__half2*>(&v.w));
    acc[0] += f0.x; acc[1] += f0.y;
    acc[2] += f1.x; acc[3] += f1.y;
    acc[4] += f2.x; acc[5] += f2.y;
    acc[6] += f3.x; acc[7] += f3.y;
}

__device__ __forceinline__ void gather_core(
    const int* __restrict__ csr, const __half* __restrict__ hc,
    int start, int d, int lane, float* acc)
{
#pragma unroll
    for (int c = 0; c < 8; c++) acc[c] = 0.f;
    const int g = lane >> 2;       // edge slot in batch (0..7)
    const int j = lane & 3;        // 16B quarter of the row
    const char* hcb = reinterpret_cast<const char*>(hc);

    const int d32 = (d < 32) ? d : 32;
    // one coalesced load of up to 32 edge ids
    int eid = (lane < d32) ? csr[start + lane] : 0;

    const int nb = d32 >> 3;       // full 8-edge batches in first 32 (0..4)
    // batch edge ids via shfl (warp-uniform branches; shfl fully convergent)
    if (nb > 0) {
        int e0 = __shfl_sync(0xffffffffu, eid, g);
        uint4 v0 = *reinterpret_cast<const uint4*>(hcb + ((size_t)e0 << 6) + (j << 4));
        if (nb > 1) {
            int e1 = __shfl_sync(0xffffffffu, eid, 8 + g);
            uint4 v1 = *reinterpret_cast<const uint4*>(hcb + ((size_t)e1 << 6) + (j << 4));
            if (nb > 2) {
                int e2 = __shfl_sync(0xffffffffu, eid, 16 + g);
                uint4 v2 = *reinterpret_cast<const uint4*>(hcb + ((size_t)e2 << 6) + (j << 4));
                if (nb > 3) {
                    int e3 = __shfl_sync(0xffffffffu, eid, 24 + g);
                    uint4 v3 = *reinterpret_cast<const uint4*>(hcb + ((size_t)e3 << 6) + (j << 4));
                    gacc(acc, v3);
                }
                gacc(acc, v2);
            }
            gacc(acc, v1);
        }
        gacc(acc, v0);
    }
    // remainder within the first 32 (rem>0 implies nb<4, so nb*8+g <= 31)
    const int rem = d32 & 7;
    {
        int idx = nb * 8 + g;
        int er = __shfl_sync(0xffffffffu, eid, (idx < 32) ? idx : 31);
        if (g < rem) {
            uint4 v = *reinterpret_cast<const uint4*>(hcb + ((size_t)er << 6) + (j << 4));
            gacc(acc, v);
        }
    }
    // beyond 32: direct loads, MLP-2
    int i = 32;
    for (; i + 16 <= d; i += 16) {
        int e0 = csr[start + i + g];
        int e1 = csr[start + i + 8 + g];
        uint4 v0 = *reinterpret_cast<const uint4*>(hcb + ((size_t)e0 << 6) + (j << 4));
        uint4 v1 = *reinterpret_cast<const uint4*>(hcb + ((size_t)e1 << 6) + (j << 4));
        gacc(acc, v0);
        gacc(acc, v1);
    }
    for (; i + 8 <= d; i += 8) {
        int e0 = csr[start + i + g];
        uint4 v0 = *reinterpret_cast<const uint4*>(hcb + ((size_t)e0 << 6) + (j << 4));
        gacc(acc, v0);
    }
    if (i < d && g < d - i) {
        int e0 = csr[start + i + g];
        uint4 v0 = *reinterpret_cast<const uint4*>(hcb + ((size_t)e0 << 6) + (j << 4));
        gacc(acc, v0);
    }
#pragma unroll
    for (int m = 4; m <= 16; m <<= 1) {
#pragma unroll
        for (int c = 0; c < 8; c++)
            acc[c] += __shfl_xor_sync(0xffffffffu, acc[c], m);
    }
}

// ===========================================================================
// Gather + layer epilogue: h = dense + relu(acc + bc), written as fp16.
// ===========================================================================
__global__ void k_gather_h(const int* __restrict__ csr,
                           const int* __restrict__ rowstart,
                           const int* __restrict__ rowend,
                           const __half* __restrict__ hc,
                           const float* __restrict__ dense_in,
                           const float* __restrict__ bc,
                           __half* __restrict__ h16)
{
    int lane = threadIdx.x & 31;
    int node = (blockIdx.x * blockDim.x + threadIdx.x) >> 5;
    if (node >= N_NODES) return;
    int start = rowstart[node];
    int d = rowend[node] - start;
    float acc[8];
    gather_core(csr, hc, start, d, lane, acc);
    if (lane < 4) {
        const float* dp  = dense_in + (size_t)node * NOUT + lane * 8;
        const float* bcp = bc + lane * 8;
        uint4 o;
        __half2* op = reinterpret_cast<__half2*>(&o);
#pragma unroll
        for (int p = 0; p < 4; p++) {
            float h0 = dp[p * 2 + 0] + fmaxf(acc[p * 2 + 0] + bcp[p * 2 + 0], 0.f);
            float h1 = dp[p * 2 + 1] + fmaxf(acc[p * 2 + 1] + bcp[p * 2 + 1], 0.f);
            op[p] = __floats2half2_rn(h0, h1);
        }
        *reinterpret_cast<uint4*>(h16 + (size_t)node * NOUT + lane * 8) = o;
    }
}

// Gather fused with final projection.
__global__ void k_gather_final(const int* __restrict__ csr,
                               const int* __restrict__ rowstart,
                               const int* __restrict__ rowend,
                               const __half* __restrict__ hc,
                               const float* __restrict__ dense_in,
                               const float* __restrict__ bc,
                               const float* __restrict__ W2,
                               const float* __restrict__ b2,
                               float* __restrict__ out)
{
    int lane = threadIdx.x & 31;
    int node = (blockIdx.x * blockDim.x + threadIdx.x) >> 5;
    if (node >= N_NODES) return;
    int start = rowstart[node];
    int d = rowend[node] - start;
    float acc[8];
    gather_core(csr, hc, start, d, lane, acc);
    float v = 0.f;
    {
        int j = lane & 3;
        const float* dp = dense_in + (size_t)node * NOUT + j * 8;
        const float* bcp = bc + j * 8;
        const float* w2p = W2 + j * 8;
#pragma unroll
        for (int c = 0; c < 8; c++) {
            float h = dp[c] + fmaxf(acc[c] + bcp[c], 0.f);
            v = fmaf(h, w2p[c], v);
        }
    }
    v += __shfl_xor_sync(0xffffffffu, v, 1);
    v += __shfl_xor_sync(0xffffffffu, v, 2);
    if (lane == 0) out[node] = v + b2[0];
}

// ===========================================================================
// Split-epilogue helpers for warp-pair mma kernels.
// ===========================================================================
__device__ __forceinline__ void split_epi_upper(
    const float* acc, int rloc0, int rloc1, int tg,
    const float* __restrict__ bm1, const float* __restrict__ bm2,
    float* __restrict__ Ps)
{
#pragma unroll
    for (int j = 0; j < 4; j++) {
        int nb = j * 8 + tg * 2;
        float b10 = bm1[nb], b11 = bm1[nb + 1];
        float b20 = bm2[nb], b21 = bm2[nb + 1];
        const float* aM1 = acc + j * 4;
        const float* aM2 = acc + (j + 4) * 4;
        float2 p0 = make_float2(fmaxf((aM1[0] + b10) * (aM2[0] + b20), 0.f),
                                fmaxf((aM1[1] + b11) * (aM2[1] + b21), 0.f));
        float2 p1 = make_float2(fmaxf((aM1[2] + b10) * (aM2[2] + b20), 0.f),
                                fmaxf((aM1[3] + b11) * (aM2[3] + b21), 0.f));
        *reinterpret_cast<float2*>(Ps + rloc0 * PSTRIDE + nb) = p0;
        *reinterpret_cast<float2*>(Ps + rloc1 * PSTRIDE + nb) = p1;
    }
}

__device__ __forceinline__ void split_epi_lower(
    const float* acc, int row0, int row1, int rloc0, int rloc1, int tg,
    const float* __restrict__ ba, const float* __restrict__ Ps,
    __half* __restrict__ hc, float* __restrict__ dense)
{
    bool v0 = row0 < N_NODES;
    bool v1 = row1 < N_NODES;
#pragma unroll
    for (int j = 0; j < 4; j++) {
        int nb = j * 8 + tg * 2;
        const float* aC = acc + j * 4;
        const float* aA = acc + (j + 4) * 4;
        float ba0 = ba[nb], ba1 = ba[nb + 1];
        if (v0) {
            *reinterpret_cast<__half2*>(hc + (size_t)row0 * NOUT + nb) =
                __floats2half2_rn(aC[0], aC[1]);
            float2 p = *reinterpret_cast<const float2*>(Ps + rloc0 * PSTRIDE + nb);
            float d0 = fmaxf(aA[0] + ba0, 0.f) + p.x;
            float d1 = fmaxf(aA[1] + ba1, 0.f) + p.y;
            *reinterpret_cast<float2*>(dense + (size_t)row0 * NOUT + nb) =
                make_float2(d0, d1);
        }
        if (v1) {
            *reinterpret_cast<__half2*>(hc + (size_t)row1 * NOUT + nb) =
                __floats2half2_rn(aC[2], aC[3]);
            float2 p = *reinterpret_cast<const float2*>(Ps + rloc1 * PSTRIDE + nb);
            float d2 = fmaxf(aA[2] + ba0, 0.f) + p.x;
            float d3 = fmaxf(aA[3] + ba1, 0.f) + p.y;
            *reinterpret_cast<float2*>(dense + (size_t)row1 * NOUT + nb) =
                make_float2(d2, d3);
        }
    }
}

// ===========================================================================
// Layer-1 GEMM, warp-pair form: 512 thr / 16 warps, acc[32]/warp, 2 CTAs/SM.
// ===========================================================================
__global__ __launch_bounds__(512, 2)
void k_layer1_mma(const float* __restrict__ x,
                  const float* __restrict__ Wc,
                  const float* __restrict__ Wa, const float* __restrict__ ba,
                  const float* __restrict__ Wm1, const float* __restrict__ bm1,
                  const float* __restrict__ Wm2, const float* __restrict__ bm2,
                  __half* __restrict__ hc, float* __restrict__ dense)
{
    extern __shared__ uint32_t smemBuf[];
    uint32_t* Bs = smemBuf;                       // [128][BSTRIDE]
    float* Ps = reinterpret_cast<float*>(smemBuf + F_IN * BSTRIDE);  // [128][PSTRIDE]
    const int tid = threadIdx.x;

    const float* Ws[4] = { Wc, Wa, Wm1, Wm2 };
    for (int idx = tid; idx < F_IN * 128; idx += 512) {
        int k = idx >> 7;
        int n = idx & 127;
        Bs[k * BSTRIDE + n] = f2tf32(Ws[n >> 5][k * NOUT + (n & 31)]);
    }
    __syncthreads();

    const int w = tid >> 5;
    const int half = w >> 3;
    const int wl = w & 7;
    const int lane = tid & 31;
    const int g = lane >> 2;
    const int tg = lane & 3;
    const int rloc0 = wl * 16 + g;
    const int rloc1 = rloc0 + 8;
    const int row0 = blockIdx.x * 128 + rloc0;
    const int row1 = blockIdx.x * 128 + rloc1;
    const float* xr0 = x + (size_t)((row0 < N_NODES) ? row0 : N_NODES - 1) * F_IN;
    const float* xr1 = x + (size_t)((row1 < N_NODES) ? row1 : N_NODES - 1) * F_IN;
    const int nbase = half * 64;

    float acc[32];
#pragma unroll
    for (int i = 0; i < 32; i++) acc[i] = 0.f;

#pragma unroll
    for (int kb = 0; kb < F_IN; kb += 8) {
        uint32_t a0 = f2tf32(xr0[kb + tg]);
        uint32_t a1 = f2tf32(xr1[kb + tg]);
        uint32_t a2 = f2tf32(xr0[kb + tg + 4]);
        uint32_t a3 = f2tf32(xr1[kb + tg + 4]);
        const uint32_t* Bk0 = Bs + (kb + tg) * BSTRIDE + nbase;
        const uint32_t* Bk1 = Bs + (kb + tg + 4) * BSTRIDE + nbase;
#pragma unroll
        for (int j = 0; j < 8; j++) {
            uint32_t b0 = Bk0[j * 8 + g];
            uint32_t b1 = Bk1[j * 8 + g];
            mma_tf32(acc[j * 4 + 0], acc[j * 4 + 1], acc[j * 4 + 2], acc[j * 4 + 3],
                     a0, a1, a2, a3, b0, b1);
        }
    }

    if (half == 1)
        split_epi_upper(acc, rloc0, rloc1, tg, bm1, bm2, Ps);
    __syncthreads();
    if (half == 0)
        split_epi_lower(acc, row0, row1, rloc0, rloc1, tg, ba, Ps, hc, dense);
}

// ===========================================================================
// K_mid GEMM, warp-pair form (K=32). h read as fp16 handoff, staged to smem.
// ===========================================================================
__global__ __launch_bounds__(512, 2)
void k_mid_mma(const __half* __restrict__ h16,
               const float* __restrict__ Wc,
               const float* __restrict__ Wa, const float* __restrict__ ba,
               const float* __restrict__ Wm1, const float* __restrict__ bm1,
               const float* __restrict__ Wm2, const float* __restrict__ bm2,
               __half* __restrict__ hc, float* __restrict__ dense_out)
{
    extern __shared__ uint32_t smemBuf[];
    uint32_t* Bs = smemBuf;                            // [32][BSTRIDE]
    uint32_t* Hs = smemBuf + NOUT * BSTRIDE;           // [128][HSTRIDE]
    float* Ps = reinterpret_cast<float*>(Hs + 128 * HSTRIDE);  // [128][PSTRIDE]
    const int tid = threadIdx.x;
    const int node0b = blockIdx.x * 128;

    const float* Ws[4] = { Wc, Wa, Wm1, Wm2 };
    for (int idx = tid; idx < NOUT * 128; idx += 512) {
        int k = idx >> 7;
        int n = idx & 127;
        Bs[k * BSTRIDE + n] = f2tf32(Ws[n >> 5][k * NOUT + (n & 31)]);
    }
#pragma unroll
    for (int i = 0; i < 4; i++) {
        int idx = i * 512 + tid;
        int r = idx >> 4;
        int c2 = idx & 15;
        int node = node0b + r;
        float2 f = make_float2(0.f, 0.f);
        if (node < N_NODES) {
            __half2 hv = *reinterpret_cast<const __half2*>(
                h16 + (size_t)node * NOUT + c2 * 2);
            f = __half22float2(hv);
        }
        Hs[r * HSTRIDE + c2 * 2 + 0] = f2tf32(f.x);
        Hs[r * HSTRIDE + c2 * 2 + 1] = f2tf32(f.y);
    }
    __syncthreads();

    const int w = tid >> 5;
    const int half = w >> 3;
    const int wl = w & 7;
    const int lane = tid & 31;
    const int g = lane >> 2;
    const int tg = lane & 3;
    const int rloc0 = wl * 16 + g;
    const int rloc1 = rloc0 + 8;
    const int row0 = node0b + rloc0;
    const int row1 = node0b + rloc1;
    const int nbase = half * 64;

    float acc[32];
#pragma unroll
    for (int i = 0; i < 32; i++) acc[i] = 0.f;

#pragma unroll
    for (int kb = 0; kb < NOUT; kb += 8) {
        uint32_t a0 = Hs[rloc0 * HSTRIDE + kb + tg];
        uint32_t a1 = Hs[rloc1 * HSTRIDE + kb + tg];
        uint32_t a2 = Hs[rloc0 * HSTRIDE + kb + tg + 4];
        uint32_t a3 = Hs[rloc1 * HSTRIDE + kb + tg + 4];
        const uint32_t* Bk0 = Bs + (kb + tg) * BSTRIDE + nbase;
        const uint32_t* Bk1 = Bs + (kb + tg + 4) * BSTRIDE + nbase;
#pragma unroll
        for (int j = 0; j < 8; j++) {
            uint32_t b0 = Bk0[j * 8 + g];
            uint32_t b1 = Bk1[j * 8 + g];
            mma_tf32(acc[j * 4 + 0], acc[j * 4 + 1], acc[j * 4 + 2], acc[j * 4 + 3],
                     a0, a1, a2, a3, b0, b1);
        }
    }

    if (half == 1)
        split_epi_upper(acc, rloc0, rloc1, tg, bm1, bm2, Ps);
    __syncthreads();
    if (half == 0)
        split_epi_lower(acc, row0, row1, rloc0, rloc1, tg, ba, Ps, hc, dense_out);
}

// ===========================================================================

extern "C" void kernel_launch(void* const* d_in, const int* in_sizes, int n_in,
                              void* d_out, int out_size)
{
    const float* x   = (const float*)d_in[0];
    const int* ei    = (const int*)d_in[1];
    const int* src   = ei;
    const int* dst   = ei + N_EDGES;
    const float* Wc1 = (const float*)d_in[2];  const float* bc1 = (const float*)d_in[3];
    const float* Wc2 = (const float*)d_in[4];  const float* bc2 = (const float*)d_in[5];
    const float* Wc3 = (const float*)d_in[6];  const float* bc3 = (const float*)d_in[7];
    const float* W11 = (const float*)d_in[8];  const float* b11 = (const float*)d_in[9];
    const float* W12 = (const float*)d_in[10]; const float* b12 = (const float*)d_in[11];
    const float* W13 = (const float*)d_in[12]; const float* b13 = (const float*)d_in[13];
    const float* W21 = (const float*)d_in[14]; const float* b21 = (const float*)d_in[15];
    const float* W22 = (const float*)d_in[16]; const float* b22 = (const float*)d_in[17];
    const float* W23 = (const float*)d_in[18]; const float* b23 = (const float*)d_in[19];
    const float* W31 = (const float*)d_in[20]; const float* b31 = (const float*)d_in[21];
    const float* W32 = (const float*)d_in[22]; const float* b32 = (const float*)d_in[23];
    const float* W33 = (const float*)d_in[24]; const float* b33 = (const float*)d_in[25];
    const float* W2  = (const float*)d_in[26]; const float* b2  = (const float*)d_in[27];
    float* out = (float*)d_out;

    __half *hc, *h16;
    float* dense;
    int *deg, *rowstart, *cursor, *counter, *csr;
    cudaGetSymbolAddress((void**)&hc,       g_hc16);
    cudaGetSymbolAddress((void**)&h16,      g_h16);
    cudaGetSymbolAddress((void**)&dense,    g_dense);
    cudaGetSymbolAddress((void**)&deg,      g_deg);
    cudaGetSymbolAddress((void**)&rowstart, g_rowstart);
    cudaGetSymbolAddress((void**)&cursor,   g_cursor);
    cudaGetSymbolAddress((void**)&counter,  g_counter);
    cudaGetSymbolAddress((void**)&csr,      g_csr);

    const int EDGE_BLOCKS = (N_EDGES + 255) / 256;
    const int HIST_BLOCKS = (N_EDGES / 4 + 255) / 256;
    const int GATH_BLOCKS = (N_NODES * 32 + 255) / 256;
    const int MMA_BLOCKS  = (N_NODES + 127) / 128;   // 782

    const int L1_SMEM  = (F_IN * BSTRIDE) * 4 + 128 * PSTRIDE * 4;           // 87040
    const int MID_SMEM = (NOUT * BSTRIDE + 128 * HSTRIDE) * 4
                       + 128 * PSTRIDE * 4;                                   // 53248
    cudaFuncSetAttribute(k_layer1_mma, cudaFuncAttributeMaxDynamicSharedMemorySize,
                         L1_SMEM);
    cudaFuncSetAttribute(k_mid_mma, cudaFuncAttributeMaxDynamicSharedMemorySize,
                         MID_SMEM);

    // Side stream + events (created once; host-side only).
    static cudaStream_t s2 = nullptr;
    static cudaEvent_t evRoot = nullptr, evJoin = nullptr;
    if (s2 == nullptr) {
        cudaStreamCreateWithFlags(&s2, cudaStreamNonBlocking);
        cudaEventCreateWithFlags(&evRoot, cudaEventDisableTiming);
        cudaEventCreateWithFlags(&evJoin, cudaEventDisableTiming);
    }

    // Fork: CSR build on s2, layer-1 GEMM on the main stream.
    cudaEventRecord(evRoot, 0);
    cudaStreamWaitEvent(s2, evRoot, 0);

    cudaMemsetAsync(deg, 0, N_NODES * sizeof(int), s2);
    cudaMemsetAsync(counter, 0, sizeof(int), s2);
    k_hist<<<HIST_BLOCKS, 256, 0, s2>>>(dst, deg);
    k_scanA<<<SCAN_NBLK, SCAN_BLOCK, 0, s2>>>(deg, rowstart, cursor, counter);
    k_fill<<<EDGE_BLOCKS, 256, 0, s2>>>(src, dst, cursor, csr);
    cudaEventRecord(evJoin, s2);

    k_layer1_mma<<<MMA_BLOCKS, 512, L1_SMEM>>>(x, Wc1, W11, b11, W12, b12,
                                               W13, b13, hc, dense);

    cudaStreamWaitEvent(0, evJoin, 0);

    // Layer 2: gather (+ layer-1 epilogue -> h1 fp16), then mid GEMM
    k_gather_h<<<GATH_BLOCKS, 256>>>(csr, rowstart, cursor, hc, dense, bc1, h16);
    k_mid_mma<<<MMA_BLOCKS, 512, MID_SMEM>>>(h16, Wc2, W21, b21, W22, b22,
                                             W23, b23, hc, dense);
    // Layer 3
    k_gather_h<<<GATH_BLOCKS, 256>>>(csr, rowstart, cursor, hc, dense, bc2, h16);
    k_mid_mma<<<MMA_BLOCKS, 512, MID_SMEM>>>(h16, Wc3, W31, b31, W32, b32,
                                             W33, b33, hc, dense);
    // Final
    k_gather_final<<<GATH_BLOCKS, 256>>>(csr, rowstart, cursor, hc, dense, bc3,
                                         W2, b2, out);
}

// round 16
// speedup vs baseline: 1.0308x; 1.0308x over previous
#include <cuda_runtime.h>
#include <cuda_fp16.h>
#include <cstdint>

#define N_NODES 100000
#define N_EDGES 3200000
#define F_IN 128
#define NOUT 32

#define SCAN_BLOCK 1024
#define SCAN_NBLK ((N_NODES + SCAN_BLOCK - 1) / SCAN_BLOCK)   // 98

// B-tile stride: pattern (tg*S + j*8 + g) needs S % 32 == 8 -> 136
// H-tile stride: pattern (g*S + tg)      needs S % 32 == 4 -> 36
#define BSTRIDE 136
#define HSTRIDE 36
#define PSTRIDE 34

// Scratch (allocation-free: __device__ globals)
__device__ __half g_hc16[N_NODES * NOUT];   // conv branch, gather source (fp16)
__device__ __half g_h16[N_NODES * NOUT];    // layer output h (fp16 handoff)
__device__ float  g_dense[N_NODES * NOUT];
__device__ int    g_deg[N_NODES];
__device__ int    g_rowstart[N_NODES];
__device__ int    g_cursor[N_NODES];        // after fill: row END
__device__ int    g_counter[1];
__device__ int    g_csr[N_EDGES];

__device__ __forceinline__ uint32_t f2tf32(float f) {
    uint32_t r;
    asm("cvt.rna.tf32.f32 %0, %1;" : "=r"(r) : "f"(f));
    return r;
}

__device__ __forceinline__ void mma_tf32(float& d0, float& d1, float& d2, float& d3,
                                         uint32_t a0, uint32_t a1, uint32_t a2,
                                         uint32_t a3, uint32_t b0, uint32_t b1) {
    asm volatile(
        "mma.sync.aligned.m16n8k8.row.col.f32.tf32.tf32.f32 "
        "{%0,%1,%2,%3}, {%4,%5,%6,%7}, {%8,%9}, {%0,%1,%2,%3};"
        : "+f"(d0), "+f"(d1), "+f"(d2), "+f"(d3)
        : "r"(a0), "r"(a1), "r"(a2), "r"(a3), "r"(b0), "r"(b1));
}

// ===========================================================================
// CSR build: zero -> hist(int4) -> scanA -> fill   (4 kernels, no memsets so
// the ncu -s 5 sample window lands on the first gather)
// ===========================================================================
__global__ void k_zero(int* __restrict__ deg, int* __restrict__ counter)
{
    int i = blockIdx.x * blockDim.x + threadIdx.x;
    if (i < N_NODES) deg[i] = 0;
    if (i == 0) counter[0] = 0;
}

__global__ void k_hist(const int* __restrict__ dst, int* __restrict__ deg)
{
    int t = blockIdx.x * blockDim.x + threadIdx.x;
    int e4 = t * 4;
    if (e4 + 4 <= N_EDGES) {
        int4 d = *reinterpret_cast<const int4*>(dst + e4);
        atomicAdd(&deg[d.x], 1);
        atomicAdd(&deg[d.y], 1);
        atomicAdd(&deg[d.z], 1);
        atomicAdd(&deg[d.w], 1);
    } else {
        for (int e = e4; e < N_EDGES; e++)
            atomicAdd(&deg[dst[e]], 1);
    }
}

// One-shot scan (bases non-monotonic; per-node ranges disjoint — sufficient).
__global__ void k_scanA(const int* __restrict__ deg, int* __restrict__ rowstart,
                        int* __restrict__ cursor, int* __restrict__ counter)
{
    __shared__ int sh[SCAN_BLOCK];
    __shared__ int base_sh;
    int i = blockIdx.x * SCAN_BLOCK + threadIdx.x;
    int v = (i < N_NODES) ? deg[i] : 0;
    sh[threadIdx.x] = v;
    __syncthreads();
    for (int off = 1; off < SCAN_BLOCK; off <<= 1) {
        int t = (threadIdx.x >= off) ? sh[threadIdx.x - off] : 0;
        __syncthreads();
        sh[threadIdx.x] += t;
        __syncthreads();
    }
    if (threadIdx.x == SCAN_BLOCK - 1)
        base_sh = atomicAdd(counter, sh[SCAN_BLOCK - 1]);
    __syncthreads();
    if (i < N_NODES) {
        int r = base_sh + sh[threadIdx.x] - v;
        rowstart[i] = r;
        cursor[i] = r;
    }
}

__global__ void k_fill(const int* __restrict__ src, const int* __restrict__ dst,
                       int* __restrict__ cursor, int* __restrict__ csr)
{
    int e = blockIdx.x * blockDim.x + threadIdx.x;
    if (e < N_EDGES) {
        int pos = atomicAdd(&cursor[dst[e]], 1);
        csr[pos] = src[e];
    }
}

// ===========================================================================
// Edge-parallel gather core (R13 form): warp per node; MLP-2 of 8-edge
// LDG.128 batches (4 lanes/edge, lane = 16B quarter). fp32 accumulate.
// ===========================================================================
__device__ __forceinline__ void gacc(float* acc, uint4 v)
{
    float2 f0 = __half22float2(*reinterpret_cast<__half2*>(&v.x));
    float2 f1 = __half22float2(*reinterpret_cast<__half2*>(&v.y));
    float2 f2 = __half22float2(*reinterpret_cast<__half2*>(&v.z));
    float2 f3 = __half22float2(*reinterpret_cast<__half2*>(&v.w));
    acc[0] += f0.x; acc[1] += f0.y;
    acc[2] += f1.x; acc[3] += f1.y;
    acc[4] += f2.x; acc[5] += f2.y;
    acc[6] += f3.x; acc[7] += f3.y;
}

__device__ __forceinline__ void gather_core(
    const int* __restrict__ csr, const __half* __restrict__ hc,
    int start, int d, int lane, float* acc)
{
#pragma unroll
    for (int c = 0; c < 8; c++) acc[c] = 0.f;
    const int g = lane >> 2;
    const int j = lane & 3;
    const char* hcb = reinterpret_cast<const char*>(hc);
    int i = 0;
    for (; i + 16 <= d; i += 16) {
        int e0 = csr[start + i + g];
        int e1 = csr[start + i + 8 + g];
        uint4 v0 = *reinterpret_cast<const uint4*>(hcb + ((size_t)e0 << 6) + (j << 4));
        uint4 v1 = *reinterpret_cast<const uint4*>(hcb + ((size_t)e1 << 6) + (j << 4));
        gacc(acc, v0);
        gacc(acc, v1);
    }
    for (; i + 8 <= d; i += 8) {
        int e0 = csr[start + i + g];
        uint4 v0 = *reinterpret_cast<const uint4*>(hcb + ((size_t)e0 << 6) + (j << 4));
        gacc(acc, v0);
    }
    if (i < d && g < d - i) {
        int e0 = csr[start + i + g];
        uint4 v0 = *reinterpret_cast<const uint4*>(hcb + ((size_t)e0 << 6) + (j << 4));
        gacc(acc, v0);
    }
#pragma unroll
    for (int m = 4; m <= 16; m <<= 1) {
#pragma unroll
        for (int c = 0; c < 8; c++)
            acc[c] += __shfl_xor_sync(0xffffffffu, acc[c], m);
    }
}

// ===========================================================================
// Gather + layer epilogue: h = dense + relu(acc + bc), written as fp16.
// ===========================================================================
__global__ __launch_bounds__(512)
void k_gather_h(const int* __restrict__ csr,
                const int* __restrict__ rowstart,
                const int* __restrict__ rowend,
                const __half* __restrict__ hc,
                const float* __restrict__ dense_in,
                const float* __restrict__ bc,
                __half* __restrict__ h16)
{
    int lane = threadIdx.x & 31;
    int node = (blockIdx.x * blockDim.x + threadIdx.x) >> 5;
    if (node >= N_NODES) return;
    int start = rowstart[node];
    int d = rowend[node] - start;
    float acc[8];
    gather_core(csr, hc, start, d, lane, acc);
    if (lane < 4) {
        const float* dp  = dense_in + (size_t)node * NOUT + lane * 8;
        const float* bcp = bc + lane * 8;
        uint4 o;
        __half2* op = reinterpret_cast<__half2*>(&o);
#pragma unroll
        for (int p = 0; p < 4; p++) {
            float h0 = dp[p * 2 + 0] + fmaxf(acc[p * 2 + 0] + bcp[p * 2 + 0], 0.f);
            float h1 = dp[p * 2 + 1] + fmaxf(acc[p * 2 + 1] + bcp[p * 2 + 1], 0.f);
            op[p] = __floats2half2_rn(h0, h1);
        }
        *reinterpret_cast<uint4*>(h16 + (size_t)node * NOUT + lane * 8) = o;
    }
}

// Gather fused with final projection.
__global__ __launch_bounds__(512)
void k_gather_final(const int* __restrict__ csr,
                    const int* __restrict__ rowstart,
                    const int* __restrict__ rowend,
                    const __half* __restrict__ hc,
                    const float* __restrict__ dense_in,
                    const float* __restrict__ bc,
                    const float* __restrict__ W2,
                    const float* __restrict__ b2,
                    float* __restrict__ out)
{
    int lane = threadIdx.x & 31;
    int node = (blockIdx.x * blockDim.x + threadIdx.x) >> 5;
    if (node >= N_NODES) return;
    int start = rowstart[node];
    int d = rowend[node] - start;
    float acc[8];
    gather_core(csr, hc, start, d, lane, acc);
    float v = 0.f;
    {
        int j = lane & 3;
        const float* dp = dense_in + (size_t)node * NOUT + j * 8;
        const float* bcp = bc + j * 8;
        const float* w2p = W2 + j * 8;
#pragma unroll
        for (int c = 0; c < 8; c++) {
            float h = dp[c] + fmaxf(acc[c] + bcp[c], 0.f);
            v = fmaf(h, w2p[c], v);
        }
    }
    v += __shfl_xor_sync(0xffffffffu, v, 1);
    v += __shfl_xor_sync(0xffffffffu, v, 2);
    if (lane == 0) out[node] = v + b2[0];
}

// ===========================================================================
// Split-epilogue helpers for warp-pair mma kernels.
// ===========================================================================
__device__ __forceinline__ void split_epi_upper(
    const float* acc, int rloc0, int rloc1, int tg,
    const float* __restrict__ bm1, const float* __restrict__ bm2,
    float* __restrict__ Ps)
{
#pragma unroll
    for (int j = 0; j < 4; j++) {
        int nb = j * 8 + tg * 2;
        float b10 = bm1[nb], b11 = bm1[nb + 1];
        float b20 = bm2[nb], b21 = bm2[nb + 1];
        const float* aM1 = acc + j * 4;
        const float* aM2 = acc + (j + 4) * 4;
        float2 p0 = make_float2(fmaxf((aM1[0] + b10) * (aM2[0] + b20), 0.f),
                                fmaxf((aM1[1] + b11) * (aM2[1] + b21), 0.f));
        float2 p1 = make_float2(fmaxf((aM1[2] + b10) * (aM2[2] + b20), 0.f),
                                fmaxf((aM1[3] + b11) * (aM2[3] + b21), 0.f));
        *reinterpret_cast<float2*>(Ps + rloc0 * PSTRIDE + nb) = p0;
        *reinterpret_cast<float2*>(Ps + rloc1 * PSTRIDE + nb) = p1;
    }
}

__device__ __forceinline__ void split_epi_lower(
    const float* acc, int row0, int row1, int rloc0, int rloc1, int tg,
    const float* __restrict__ ba, const float* __restrict__ Ps,
    __half* __restrict__ hc, float* __restrict__ dense)
{
    bool v0 = row0 < N_NODES;
    bool v1 = row1 < N_NODES;
#pragma unroll
    for (int j = 0; j < 4; j++) {
        int nb = j * 8 + tg * 2;
        const float* aC = acc + j * 4;
        const float* aA = acc + (j + 4) * 4;
        float ba0 = ba[nb], ba1 = ba[nb + 1];
        if (v0) {
            *reinterpret_cast<__half2*>(hc + (size_t)row0 * NOUT + nb) =
                __floats2half2_rn(aC[0], aC[1]);
            float2 p = *reinterpret_cast<const float2*>(Ps + rloc0 * PSTRIDE + nb);
            float d0 = fmaxf(aA[0] + ba0, 0.f) + p.x;
            float d1 = fmaxf(aA[1] + ba1, 0.f) + p.y;
            *reinterpret_cast<float2*>(dense + (size_t)row0 * NOUT + nb) =
                make_float2(d0, d1);
        }
        if (v1) {
            *reinterpret_cast<__half2*>(hc + (size_t)row1 * NOUT + nb) =
                __floats2half2_rn(aC[2], aC[3]);
            float2 p = *reinterpret_cast<const float2*>(Ps + rloc1 * PSTRIDE + nb);
            float d2 = fmaxf(aA[2] + ba0, 0.f) + p.x;
            float d3 = fmaxf(aA[3] + ba1, 0.f) + p.y;
            *reinterpret_cast<float2*>(dense + (size_t)row1 * NOUT + nb) =
                make_float2(d2, d3);
        }
    }
}

// ===========================================================================
// Layer-1 GEMM, warp-pair form: 512 thr / 16 warps, acc[32]/warp, 2 CTAs/SM.
// ===========================================================================
__global__ __launch_bounds__(512, 2)
void k_layer1_mma(const float* __restrict__ x,
                  const float* __restrict__ Wc,
                  const float* __restrict__ Wa, const float* __restrict__ ba,
                  const float* __restrict__ Wm1, const float* __restrict__ bm1,
                  const float* __restrict__ Wm2, const float* __restrict__ bm2,
                  __half* __restrict__ hc, float* __restrict__ dense)
{
    extern __shared__ uint32_t smemBuf[];
    uint32_t* Bs = smemBuf;                       // [128][BSTRIDE]
    float* Ps = reinterpret_cast<float*>(smemBuf + F_IN * BSTRIDE);  // [128][PSTRIDE]
    const int tid = threadIdx.x;

    const float* Ws[4] = { Wc, Wa, Wm1, Wm2 };
    for (int idx = tid; idx < F_IN * 128; idx += 512) {
        int k = idx >> 7;
        int n = idx & 127;
        Bs[k * BSTRIDE + n] = f2tf32(Ws[n >> 5][k * NOUT + (n & 31)]);
    }
    __syncthreads();

    const int w = tid >> 5;
    const int half = w >> 3;
    const int wl = w & 7;
    const int lane = tid & 31;
    const int g = lane >> 2;
    const int tg = lane & 3;
    const int rloc0 = wl * 16 + g;
    const int rloc1 = rloc0 + 8;
    const int row0 = blockIdx.x * 128 + rloc0;
    const int row1 = blockIdx.x * 128 + rloc1;
    const float* xr0 = x + (size_t)((row0 < N_NODES) ? row0 : N_NODES - 1) * F_IN;
    const float* xr1 = x + (size_t)((row1 < N_NODES) ? row1 : N_NODES - 1) * F_IN;
    const int nbase = half * 64;

    float acc[32];
#pragma unroll
    for (int i = 0; i < 32; i++) acc[i] = 0.f;

#pragma unroll
    for (int kb = 0; kb < F_IN; kb += 8) {
        uint32_t a0 = f2tf32(xr0[kb + tg]);
        uint32_t a1 = f2tf32(xr1[kb + tg]);
        uint32_t a2 = f2tf32(xr0[kb + tg + 4]);
        uint32_t a3 = f2tf32(xr1[kb + tg + 4]);
        const uint32_t* Bk0 = Bs + (kb + tg) * BSTRIDE + nbase;
        const uint32_t* Bk1 = Bs + (kb + tg + 4) * BSTRIDE + nbase;
#pragma unroll
        for (int j = 0; j < 8; j++) {
            uint32_t b0 = Bk0[j * 8 + g];
            uint32_t b1 = Bk1[j * 8 + g];
            mma_tf32(acc[j * 4 + 0], acc[j * 4 + 1], acc[j * 4 + 2], acc[j * 4 + 3],
                     a0, a1, a2, a3, b0, b1);
        }
    }

    if (half == 1)
        split_epi_upper(acc, rloc0, rloc1, tg, bm1, bm2, Ps);
    __syncthreads();
    if (half == 0)
        split_epi_lower(acc, row0, row1, rloc0, rloc1, tg, ba, Ps, hc, dense);
}

// ===========================================================================
// K_mid GEMM, warp-pair form (K=32). h read as fp16 handoff, staged to smem.
// ===========================================================================
__global__ __launch_bounds__(512, 2)
void k_mid_mma(const __half* __restrict__ h16,
               const float* __restrict__ Wc,
               const float* __restrict__ Wa, const float* __restrict__ ba,
               const float* __restrict__ Wm1, const float* __restrict__ bm1,
               const float* __restrict__ Wm2, const float* __restrict__ bm2,
               __half* __restrict__ hc, float* __restrict__ dense_out)
{
    extern __shared__ uint32_t smemBuf[];
    uint32_t* Bs = smemBuf;                            // [32][BSTRIDE]
    uint32_t* Hs = smemBuf + NOUT * BSTRIDE;           // [128][HSTRIDE]
    float* Ps = reinterpret_cast<float*>(Hs + 128 * HSTRIDE);  // [128][PSTRIDE]
    const int tid = threadIdx.x;
    const int node0b = blockIdx.x * 128;

    const float* Ws[4] = { Wc, Wa, Wm1, Wm2 };
    for (int idx = tid; idx < NOUT * 128; idx += 512) {
        int k = idx >> 7;
        int n = idx & 127;
        Bs[k * BSTRIDE + n] = f2tf32(Ws[n >> 5][k * NOUT + (n & 31)]);
    }
#pragma unroll
    for (int i = 0; i < 4; i++) {
        int idx = i * 512 + tid;
        int r = idx >> 4;
        int c2 = idx & 15;
        int node = node0b + r;
        float2 f = make_float2(0.f, 0.f);
        if (node < N_NODES) {
            __half2 hv = *reinterpret_cast<const __half2*>(
                h16 + (size_t)node * NOUT + c2 * 2);
            f = __half22float2(hv);
        }
        Hs[r * HSTRIDE + c2 * 2 + 0] = f2tf32(f.x);
        Hs[r * HSTRIDE + c2 * 2 + 1] = f2tf32(f.y);
    }
    __syncthreads();

    const int w = tid >> 5;
    const int half = w >> 3;
    const int wl = w & 7;
    const int lane = tid & 31;
    const int g = lane >> 2;
    const int tg = lane & 3;
    const int rloc0 = wl * 16 + g;
    const int rloc1 = rloc0 + 8;
    const int row0 = node0b + rloc0;
    const int row1 = node0b + rloc1;
    const int nbase = half * 64;

    float acc[32];
#pragma unroll
    for (int i = 0; i < 32; i++) acc[i] = 0.f;

#pragma unroll
    for (int kb = 0; kb < NOUT; kb += 8) {
        uint32_t a0 = Hs[rloc0 * HSTRIDE + kb + tg];
        uint32_t a1 = Hs[rloc1 * HSTRIDE + kb + tg];
        uint32_t a2 = Hs[rloc0 * HSTRIDE + kb + tg + 4];
        uint32_t a3 = Hs[rloc1 * HSTRIDE + kb + tg + 4];
        const uint32_t* Bk0 = Bs + (kb + tg) * BSTRIDE + nbase;
        const uint32_t* Bk1 = Bs + (kb + tg + 4) * BSTRIDE + nbase;
#pragma unroll
        for (int j = 0; j < 8; j++) {
            uint32_t b0 = Bk0[j * 8 + g];
            uint32_t b1 = Bk1[j * 8 + g];
            mma_tf32(acc[j * 4 + 0], acc[j * 4 + 1], acc[j * 4 + 2], acc[j * 4 + 3],
                     a0, a1, a2, a3, b0, b1);
        }
    }

    if (half == 1)
        split_epi_upper(acc, rloc0, rloc1, tg, bm1, bm2, Ps);
    __syncthreads();
    if (half == 0)
        split_epi_lower(acc, row0, row1, rloc0, rloc1, tg, ba, Ps, hc, dense_out);
}

// ===========================================================================

extern "C" void kernel_launch(void* const* d_in, const int* in_sizes, int n_in,
                              void* d_out, int out_size)
{
    const float* x   = (const float*)d_in[0];
    const int* ei    = (const int*)d_in[1];
    const int* src   = ei;
    const int* dst   = ei + N_EDGES;
    const float* Wc1 = (const float*)d_in[2];  const float* bc1 = (const float*)d_in[3];
    const float* Wc2 = (const float*)d_in[4];  const float* bc2 = (const float*)d_in[5];
    const float* Wc3 = (const float*)d_in[6];  const float* bc3 = (const float*)d_in[7];
    const float* W11 = (const float*)d_in[8];  const float* b11 = (const float*)d_in[9];
    const float* W12 = (const float*)d_in[10]; const float* b12 = (const float*)d_in[11];
    const float* W13 = (const float*)d_in[12]; const float* b13 = (const float*)d_in[13];
    const float* W21 = (const float*)d_in[14]; const float* b21 = (const float*)d_in[15];
    const float* W22 = (const float*)d_in[16]; const float* b22 = (const float*)d_in[17];
    const float* W23 = (const float*)d_in[18]; const float* b23 = (const float*)d_in[19];
    const float* W31 = (const float*)d_in[20]; const float* b31 = (const float*)d_in[21];
    const float* W32 = (const float*)d_in[22]; const float* b32 = (const float*)d_in[23];
    const float* W33 = (const float*)d_in[24]; const float* b33 = (const float*)d_in[25];
    const float* W2  = (const float*)d_in[26]; const float* b2  = (const float*)d_in[27];
    float* out = (float*)d_out;

    __half *hc, *h16;
    float* dense;
    int *deg, *rowstart, *cursor, *counter, *csr;
    cudaGetSymbolAddress((void**)&hc,       g_hc16);
    cudaGetSymbolAddress((void**)&h16,      g_h16);
    cudaGetSymbolAddress((void**)&dense,    g_dense);
    cudaGetSymbolAddress((void**)&deg,      g_deg);
    cudaGetSymbolAddress((void**)&rowstart, g_rowstart);
    cudaGetSymbolAddress((void**)&cursor,   g_cursor);
    cudaGetSymbolAddress((void**)&counter,  g_counter);
    cudaGetSymbolAddress((void**)&csr,      g_csr);

    const int EDGE_BLOCKS = (N_EDGES + 255) / 256;
    const int HIST_BLOCKS = (N_EDGES / 4 + 255) / 256;
    const int NVEC_BLOCKS = (N_NODES + 255) / 256;
    const int GATH_BLOCKS = (N_NODES * 32 + 511) / 512;
    const int MMA_BLOCKS  = (N_NODES + 127) / 128;   // 782

    const int L1_SMEM  = (F_IN * BSTRIDE) * 4 + 128 * PSTRIDE * 4;           // 87040
    const int MID_SMEM = (NOUT * BSTRIDE + 128 * HSTRIDE) * 4
                       + 128 * PSTRIDE * 4;                                   // 53248
    cudaFuncSetAttribute(k_layer1_mma, cudaFuncAttributeMaxDynamicSharedMemorySize,
                         L1_SMEM);
    cudaFuncSetAttribute(k_mid_mma, cudaFuncAttributeMaxDynamicSharedMemorySize,
                         MID_SMEM);

    // Side stream + events (created once; host-side only).
    static cudaStream_t s2 = nullptr;
    static cudaEvent_t evRoot = nullptr, evJoin = nullptr;
    if (s2 == nullptr) {
        cudaStreamCreateWithFlags(&s2, cudaStreamNonBlocking);
        cudaEventCreateWithFlags(&evRoot, cudaEventDisableTiming);
        cudaEventCreateWithFlags(&evJoin, cudaEventDisableTiming);
    }

    // Fork: CSR build on s2, layer-1 GEMM on the main stream.
    cudaEventRecord(evRoot, 0);
    cudaStreamWaitEvent(s2, evRoot, 0);

    k_zero<<<NVEC_BLOCKS, 256, 0, s2>>>(deg, counter);
    k_hist<<<HIST_BLOCKS, 256, 0, s2>>>(dst, deg);
    k_scanA<<<SCAN_NBLK, SCAN_BLOCK, 0, s2>>>(deg, rowstart, cursor, counter);
    k_fill<<<EDGE_BLOCKS, 256, 0, s2>>>(src, dst, cursor, csr);
    cudaEventRecord(evJoin, s2);

    k_layer1_mma<<<MMA_BLOCKS, 512, L1_SMEM>>>(x, Wc1, W11, b11, W12, b12,
                                               W13, b13, hc, dense);

    cudaStreamWaitEvent(0, evJoin, 0);

    // Layer 2: gather (+ layer-1 epilogue -> h1 fp16), then mid GEMM
    k_gather_h<<<GATH_BLOCKS, 512>>>(csr, rowstart, cursor, hc, dense, bc1, h16);
    k_mid_mma<<<MMA_BLOCKS, 512, MID_SMEM>>>(h16, Wc2, W21, b21, W22, b22,
                                             W23, b23, hc, dense);
    // Layer 3
    k_gather_h<<<GATH_BLOCKS, 512>>>(csr, rowstart, cursor, hc, dense, bc2, h16);
    k_mid_mma<<<MMA_BLOCKS, 512, MID_SMEM>>>(h16, Wc3, W31, b31, W32, b32,
                                             W33, b33, hc, dense);
    // Final
    k_gather_final<<<GATH_BLOCKS, 512>>>(csr, rowstart, cursor, hc, dense, bc3,
                                         W2, b2, out);
}

// round 17
// speedup vs baseline: 1.0455x; 1.0143x over previous
#include <cuda_runtime.h>
#include <cuda_fp16.h>
#include <cstdint>

#define N_NODES 100000
#define N_EDGES 3200000
#define F_IN 128
#define NOUT 32

#define SCAN_BLOCK 1024
#define SCAN_NBLK ((N_NODES + SCAN_BLOCK - 1) / SCAN_BLOCK)   // 98

// B-tile stride: pattern (tg*S + j*8 + g) needs S % 32 == 8 -> 136
// H-tile stride: pattern (g*S + tg)      needs S % 32 == 4 -> 36
// X-tile stride (16-wide chunks): 20 (20g distinct mod 32, +tg injective)
#define BSTRIDE 136
#define HSTRIDE 36
#define PSTRIDE 34
#define XSTRIDE 20

// Scratch (allocation-free: __device__ globals)
__device__ __half g_hc16[N_NODES * NOUT];   // conv branch, gather source (fp16)
__device__ __half g_h16[N_NODES * NOUT];    // layer output h (fp16 handoff)
__device__ float  g_dense[N_NODES * NOUT];
__device__ int    g_deg[N_NODES];
__device__ int    g_rowstart[N_NODES];
__device__ int    g_rowend[N_NODES];
__device__ int    g_rank[N_EDGES];
__device__ int    g_csr[N_EDGES];

__device__ __forceinline__ uint32_t f2tf32(float f) {
    uint32_t r;
    asm("cvt.rna.tf32.f32 %0, %1;" : "=r"(r) : "f"(f));
    return r;
}

__device__ __forceinline__ void mma_tf32(float& d0, float& d1, float& d2, float& d3,
                                         uint32_t a0, uint32_t a1, uint32_t a2,
                                         uint32_t a3, uint32_t b0, uint32_t b1) {
    asm volatile(
        "mma.sync.aligned.m16n8k8.row.col.f32.tf32.tf32.f32 "
        "{%0,%1,%2,%3}, {%4,%5,%6,%7}, {%8,%9}, {%0,%1,%2,%3};"
        : "+f"(d0), "+f"(d1), "+f"(d2), "+f"(d3)
        : "r"(a0), "r"(a1), "r"(a2), "r"(a3), "r"(b0), "r"(b1));
}

// ===========================================================================
// CSR build: zero -> hist(+rank) -> scanA -> fill(atomic-free)
// ===========================================================================
__global__ void k_zero(int* __restrict__ deg)
{
    int i = blockIdx.x * blockDim.x + threadIdx.x;
    if (i < N_NODES) deg[i] = 0;
}

// Histogram that also records each edge's arrival rank within its dst bucket.
__global__ void k_hist(const int* __restrict__ dst, int* __restrict__ deg,
                       int* __restrict__ rank)
{
    int t = blockIdx.x * blockDim.x + threadIdx.x;
    int e4 = t * 4;
    if (e4 + 4 <= N_EDGES) {
        int4 d = *reinterpret_cast<const int4*>(dst + e4);
        int4 rk;
        rk.x = atomicAdd(&deg[d.x], 1);
        rk.y = atomicAdd(&deg[d.y], 1);
        rk.z = atomicAdd(&deg[d.z], 1);
        rk.w = atomicAdd(&deg[d.w], 1);
        *reinterpret_cast<int4*>(rank + e4) = rk;
    } else {
        for (int e = e4; e < N_EDGES; e++)
            rank[e] = atomicAdd(&deg[dst[e]], 1);
    }
}

// One-shot scan: block-local exclusive scan + atomic block base (bases
// non-monotonic; per-node ranges disjoint — sufficient for the gathers).
__device__ int g_scan_counter;
__global__ void k_scanA(const int* __restrict__ deg, int* __restrict__ rowstart,
                        int* __restrict__ rowend)
{
    __shared__ int sh[SCAN_BLOCK];
    __shared__ int base_sh;
    int i = blockIdx.x * SCAN_BLOCK + threadIdx.x;
    int v = (i < N_NODES) ? deg[i] : 0;
    sh[threadIdx.x] = v;
    __syncthreads();
    for (int off = 1; off < SCAN_BLOCK; off <<= 1) {
        int t = (threadIdx.x >= off) ? sh[threadIdx.x - off] : 0;
        __syncthreads();
        sh[threadIdx.x] += t;
        __syncthreads();
    }
    if (threadIdx.x == SCAN_BLOCK - 1)
        base_sh = atomicAdd(&g_scan_counter, sh[SCAN_BLOCK - 1]);
    __syncthreads();
    if (i < N_NODES) {
        int r = base_sh + sh[threadIdx.x] - v;
        rowstart[i] = r;
        rowend[i] = r + v;
    }
}

__global__ void k_zero_counter()
{
    g_scan_counter = 0;
}

// Atomic-free fill: position = rowstart[dst] + rank (unique by construction).
__global__ void k_fill(const int* __restrict__ src, const int* __restrict__ dst,
                       const int* __restrict__ rowstart,
                       const int* __restrict__ rank, int* __restrict__ csr)
{
    int t = blockIdx.x * blockDim.x + threadIdx.x;
    int e4 = t * 4;
    if (e4 + 4 <= N_EDGES) {
        int4 d = *reinterpret_cast<const int4*>(dst + e4);
        int4 rk = *reinterpret_cast<const int4*>(rank + e4);
        int4 s = *reinterpret_cast<const int4*>(src + e4);
        csr[rowstart[d.x] + rk.x] = s.x;
        csr[rowstart[d.y] + rk.y] = s.y;
        csr[rowstart[d.z] + rk.z] = s.z;
        csr[rowstart[d.w] + rk.w] = s.w;
    } else {
        for (int e = e4; e < N_EDGES; e++)
            csr[rowstart[dst[e]] + rank[e]] = src[e];
    }
}

// ===========================================================================
// Edge-parallel gather core (R13/R16 form): warp per node; MLP-2 of 8-edge
// LDG.128 batches (4 lanes/edge, lane = 16B quarter). fp32 accumulate.
// ===========================================================================
__device__ __forceinline__ void gacc(float* acc, uint4 v)
{
    float2 f0 = __half22float2(*reinterpret_cast<__half2*>(&v.x));
    float2 f1 = __half22float2(*reinterpret_cast<__half2*>(&v.y));
    float2 f2 = __half22float2(*reinterpret_cast<__half2*>(&v.z));
    float2 f3 = __half22float2(*reinterpret_cast<__half2*>(&v.w));
    acc[0] += f0.x; acc[1] += f0.y;
    acc[2] += f1.x; acc[3] += f1.y;
    acc[4] += f2.x; acc[5] += f2.y;
    acc[6] += f3.x; acc[7] += f3.y;
}

__device__ __forceinline__ void gather_core(
    const int* __restrict__ csr, const __half* __restrict__ hc,
    int start, int d, int lane, float* acc)
{
#pragma unroll
    for (int c = 0; c < 8; c++) acc[c] = 0.f;
    const int g = lane >> 2;
    const int j = lane & 3;
    const char* hcb = reinterpret_cast<const char*>(hc);
    int i = 0;
    for (; i + 16 <= d; i += 16) {
        int e0 = csr[start + i + g];
        int e1 = csr[start + i + 8 + g];
        uint4 v0 = *reinterpret_cast<const uint4*>(hcb + ((size_t)e0 << 6) + (j << 4));
        uint4 v1 = *reinterpret_cast<const uint4*>(hcb + ((size_t)e1 << 6) + (j << 4));
        gacc(acc, v0);
        gacc(acc, v1);
    }
    for (; i + 8 <= d; i += 8) {
        int e0 = csr[start + i + g];
        uint4 v0 = *reinterpret_cast<const uint4*>(hcb + ((size_t)e0 << 6) + (j << 4));
        gacc(acc, v0);
    }
    if (i < d && g < d - i) {
        int e0 = csr[start + i + g];
        uint4 v0 = *reinterpret_cast<const uint4*>(hcb + ((size_t)e0 << 6) + (j << 4));
        gacc(acc, v0);
    }
#pragma unroll
    for (int m = 4; m <= 16; m <<= 1) {
#pragma unroll
        for (int c = 0; c < 8; c++)
            acc[c] += __shfl_xor_sync(0xffffffffu, acc[c], m);
    }
}

// ===========================================================================
// Gather + layer epilogue: h = dense + relu(acc + bc), written as fp16.
// ===========================================================================
__global__ __launch_bounds__(512)
void k_gather_h(const int* __restrict__ csr,
                const int* __restrict__ rowstart,
                const int* __restrict__ rowend,
                const __half* __restrict__ hc,
                const float* __restrict__ dense_in,
                const float* __restrict__ bc,
                __half* __restrict__ h16)
{
    int lane = threadIdx.x & 31;
    int node = (blockIdx.x * blockDim.x + threadIdx.x) >> 5;
    if (node >= N_NODES) return;
    int start = rowstart[node];
    int d = rowend[node] - start;
    float acc[8];
    gather_core(csr, hc, start, d, lane, acc);
    if (lane < 4) {
        const float* dp  = dense_in + (size_t)node * NOUT + lane * 8;
        const float* bcp = bc + lane * 8;
        uint4 o;
        __half2* op = reinterpret_cast<__half2*>(&o);
#pragma unroll
        for (int p = 0; p < 4; p++) {
            float h0 = dp[p * 2 + 0] + fmaxf(acc[p * 2 + 0] + bcp[p * 2 + 0], 0.f);
            float h1 = dp[p * 2 + 1] + fmaxf(acc[p * 2 + 1] + bcp[p * 2 + 1], 0.f);
            op[p] = __floats2half2_rn(h0, h1);
        }
        *reinterpret_cast<uint4*>(h16 + (size_t)node * NOUT + lane * 8) = o;
    }
}

// Gather fused with final projection.
__global__ __launch_bounds__(512)
void k_gather_final(const int* __restrict__ csr,
                    const int* __restrict__ rowstart,
                    const int* __restrict__ rowend,
                    const __half* __restrict__ hc,
                    const float* __restrict__ dense_in,
                    const float* __restrict__ bc,
                    const float* __restrict__ W2,
                    const float* __restrict__ b2,
                    float* __restrict__ out)
{
    int lane = threadIdx.x & 31;
    int node = (blockIdx.x * blockDim.x + threadIdx.x) >> 5;
    if (node >= N_NODES) return;
    int start = rowstart[node];
    int d = rowend[node] - start;
    float acc[8];
    gather_core(csr, hc, start, d, lane, acc);
    float v = 0.f;
    {
        int j = lane & 3;
        const float* dp = dense_in + (size_t)node * NOUT + j * 8;
        const float* bcp = bc + j * 8;
        const float* w2p = W2 + j * 8;
#pragma unroll
        for (int c = 0; c < 8; c++) {
            float h = dp[c] + fmaxf(acc[c] + bcp[c], 0.f);
            v = fmaf(h, w2p[c], v);
        }
    }
    v += __shfl_xor_sync(0xffffffffu, v, 1);
    v += __shfl_xor_sync(0xffffffffu, v, 2);
    if (lane == 0) out[node] = v + b2[0];
}

// ===========================================================================
// Split-epilogue helpers for warp-pair mma kernels.
// ===========================================================================
__device__ __forceinline__ void split_epi_upper(
    const float* acc, int rloc0, int rloc1, int tg,
    const float* __restrict__ bm1, const float* __restrict__ bm2,
    float* __restrict__ Ps)
{
#pragma unroll
    for (int j = 0; j < 4; j++) {
        int nb = j * 8 + tg * 2;
        float b10 = bm1[nb], b11 = bm1[nb + 1];
        float b20 = bm2[nb], b21 = bm2[nb + 1];
        const float* aM1 = acc + j * 4;
        const float* aM2 = acc + (j + 4) * 4;
        float2 p0 = make_float2(fmaxf((aM1[0] + b10) * (aM2[0] + b20), 0.f),
                                fmaxf((aM1[1] + b11) * (aM2[1] + b21), 0.f));
        float2 p1 = make_float2(fmaxf((aM1[2] + b10) * (aM2[2] + b20), 0.f),
                                fmaxf((aM1[3] + b11) * (aM2[3] + b21), 0.f));
        *reinterpret_cast<float2*>(Ps + rloc0 * PSTRIDE + nb) = p0;
        *reinterpret_cast<float2*>(Ps + rloc1 * PSTRIDE + nb) = p1;
    }
}

__device__ __forceinline__ void split_epi_lower(
    const float* acc, int row0, int row1, int rloc0, int rloc1, int tg,
    const float* __restrict__ ba, const float* __restrict__ Ps,
    __half* __restrict__ hc, float* __restrict__ dense)
{
    bool v0 = row0 < N_NODES;
    bool v1 = row1 < N_NODES;
#pragma unroll
    for (int j = 0; j < 4; j++) {
        int nb = j * 8 + tg * 2;
        const float* aC = acc + j * 4;
        const float* aA = acc + (j + 4) * 4;
        float ba0 = ba[nb], ba1 = ba[nb + 1];
        if (v0) {
            *reinterpret_cast<__half2*>(hc + (size_t)row0 * NOUT + nb) =
                __floats2half2_rn(aC[0], aC[1]);
            float2 p = *reinterpret_cast<const float2*>(Ps + rloc0 * PSTRIDE + nb);
            float d0 = fmaxf(aA[0] + ba0, 0.f) + p.x;
            float d1 = fmaxf(aA[1] + ba1, 0.f) + p.y;
            *reinterpret_cast<float2*>(dense + (size_t)row0 * NOUT + nb) =
                make_float2(d0, d1);
        }
        if (v1) {
            *reinterpret_cast<__half2*>(hc + (size_t)row1 * NOUT + nb) =
                __floats2half2_rn(aC[2], aC[3]);
            float2 p = *reinterpret_cast<const float2*>(Ps + rloc1 * PSTRIDE + nb);
            float d2 = fmaxf(aA[2] + ba0, 0.f) + p.x;
            float d3 = fmaxf(aA[3] + ba1, 0.f) + p.y;
            *reinterpret_cast<float2*>(dense + (size_t)row1 * NOUT + nb) =
                make_float2(d2, d3);
        }
    }
}

// ===========================================================================
// Layer-1 GEMM, warp-pair + cp.async x-staging. 512 thr / 16 warps,
// acc[32]/warp, 2 CTAs/SM. x staged in 8 double-buffered 128x16 chunks.
// Ps aliases the Xs region (used only after the mainloop; barrier-separated).
// ===========================================================================
__global__ __launch_bounds__(512, 2)
void k_layer1_mma(const float* __restrict__ x,
                  const float* __restrict__ Wc,
                  const float* __restrict__ Wa, const float* __restrict__ ba,
                  const float* __restrict__ Wm1, const float* __restrict__ bm1,
                  const float* __restrict__ Wm2, const float* __restrict__ bm2,
                  __half* __restrict__ hc, float* __restrict__ dense)
{
    extern __shared__ uint32_t smemBuf[];
    uint32_t* Bs = smemBuf;                         // [128][BSTRIDE]
    uint32_t* Xs = smemBuf + F_IN * BSTRIDE;        // [2][128][XSTRIDE]
    float* Ps = reinterpret_cast<float*>(Xs);       // aliased: [128][PSTRIDE]
    const int tid = threadIdx.x;
    const int node0b = blockIdx.x * 128;

    // async copy of one 128x16 chunk: 512 float4 slots, 1 per thread
    auto issue_chunk = [&](int c, int buf) {
        int r = tid >> 2;
        int fv = tid & 3;
        int node = node0b + r;
        if (node >= N_NODES) node = N_NODES - 1;    // clamp (outputs guarded)
        const float* srcp = x + (size_t)node * F_IN + c * 16 + fv * 4;
        uint32_t dstb = (uint32_t)__cvta_generic_to_shared(
            Xs + (size_t)buf * 128 * XSTRIDE + r * XSTRIDE + fv * 4);
        asm volatile("cp.async.ca.shared.global [%0], [%1], 16;"
                     :: "r"(dstb), "l"(srcp));
        asm volatile("cp.async.commit_group;");
    };

    issue_chunk(0, 0);

    const float* Ws[4] = { Wc, Wa, Wm1, Wm2 };
    for (int idx = tid; idx < F_IN * 128; idx += 512) {
        int k = idx >> 7;
        int n = idx & 127;
        Bs[k * BSTRIDE + n] = f2tf32(Ws[n >> 5][k * NOUT + (n & 31)]);
    }

    const int w = tid >> 5;
    const int half = w >> 3;
    const int wl = w & 7;
    const int lane = tid & 31;
    const int g = lane >> 2;
    const int tg = lane & 3;
    const int rloc0 = wl * 16 + g;
    const int rloc1 = rloc0 + 8;
    const int row0 = node0b + rloc0;
    const int row1 = node0b + rloc1;
    const int nbase = half * 64;

    float acc[32];
#pragma unroll
    for (int i = 0; i < 32; i++) acc[i] = 0.f;

#pragma unroll 1
    for (int c = 0; c < 8; c++) {
        if (c + 1 < 8) {
            issue_chunk(c + 1, (c + 1) & 1);
            asm volatile("cp.async.wait_group 1;");
        } else {
            asm volatile("cp.async.wait_group 0;");
        }
        __syncthreads();

        const uint32_t* Xb = Xs + (size_t)(c & 1) * 128 * XSTRIDE;
#pragma unroll
        for (int kb = 0; kb < 16; kb += 8) {
            uint32_t a0 = f2tf32(__uint_as_float(Xb[rloc0 * XSTRIDE + kb + tg]));
            uint32_t a1 = f2tf32(__uint_as_float(Xb[rloc1 * XSTRIDE + kb + tg]));
            uint32_t a2 = f2tf32(__uint_as_float(Xb[rloc0 * XSTRIDE + kb + tg + 4]));
            uint32_t a3 = f2tf32(__uint_as_float(Xb[rloc1 * XSTRIDE + kb + tg + 4]));
            const uint32_t* Bk0 = Bs + (c * 16 + kb + tg) * BSTRIDE + nbase;
            const uint32_t* Bk1 = Bs + (c * 16 + kb + tg + 4) * BSTRIDE + nbase;
#pragma unroll
            for (int j = 0; j < 8; j++) {
                uint32_t b0 = Bk0[j * 8 + g];
                uint32_t b1 = Bk1[j * 8 + g];
                mma_tf32(acc[j * 4 + 0], acc[j * 4 + 1], acc[j * 4 + 2],
                         acc[j * 4 + 3], a0, a1, a2, a3, b0, b1);
            }
        }
        __syncthreads();
    }

    if (half == 1)
        split_epi_upper(acc, rloc0, rloc1, tg, bm1, bm2, Ps);
    __syncthreads();
    if (half == 0)
        split_epi_lower(acc, row0, row1, rloc0, rloc1, tg, ba, Ps, hc, dense);
}

// ===========================================================================
// K_mid GEMM, warp-pair form (K=32). h read as fp16 handoff, staged to smem.
// ===========================================================================
__global__ __launch_bounds__(512, 2)
void k_mid_mma(const __half* __restrict__ h16,
               const float* __restrict__ Wc,
               const float* __restrict__ Wa, const float* __restrict__ ba,
               const float* __restrict__ Wm1, const float* __restrict__ bm1,
               const float* __restrict__ Wm2, const float* __restrict__ bm2,
               __half* __restrict__ hc, float* __restrict__ dense_out)
{
    extern __shared__ uint32_t smemBuf[];
    uint32_t* Bs = smemBuf;                            // [32][BSTRIDE]
    uint32_t* Hs = smemBuf + NOUT * BSTRIDE;           // [128][HSTRIDE]
    float* Ps = reinterpret_cast<float*>(Hs + 128 * HSTRIDE);  // [128][PSTRIDE]
    const int tid = threadIdx.x;
    const int node0b = blockIdx.x * 128;

    const float* Ws[4] = { Wc, Wa, Wm1, Wm2 };
    for (int idx = tid; idx < NOUT * 128; idx += 512) {
        int k = idx >> 7;
        int n = idx & 127;
        Bs[k * BSTRIDE + n] = f2tf32(Ws[n >> 5][k * NOUT + (n & 31)]);
    }
#pragma unroll
    for (int i = 0; i < 4; i++) {
        int idx = i * 512 + tid;
        int r = idx >> 4;
        int c2 = idx & 15;
        int node = node0b + r;
        float2 f = make_float2(0.f, 0.f);
        if (node < N_NODES) {
            __half2 hv = *reinterpret_cast<const __half2*>(
                h16 + (size_t)node * NOUT + c2 * 2);
            f = __half22float2(hv);
        }
        Hs[r * HSTRIDE + c2 * 2 + 0] = f2tf32(f.x);
        Hs[r * HSTRIDE + c2 * 2 + 1] = f2tf32(f.y);
    }
    __syncthreads();

    const int w = tid >> 5;
    const int half = w >> 3;
    const int wl = w & 7;
    const int lane = tid & 31;
    const int g = lane >> 2;
    const int tg = lane & 3;
    const int rloc0 = wl * 16 + g;
    const int rloc1 = rloc0 + 8;
    const int row0 = node0b + rloc0;
    const int row1 = node0b + rloc1;
    const int nbase = half * 64;

    float acc[32];
#pragma unroll
    for (int i = 0; i < 32; i++) acc[i] = 0.f;

#pragma unroll
    for (int kb = 0; kb < NOUT; kb += 8) {
        uint32_t a0 = Hs[rloc0 * HSTRIDE + kb + tg];
        uint32_t a1 = Hs[rloc1 * HSTRIDE + kb + tg];
        uint32_t a2 = Hs[rloc0 * HSTRIDE + kb + tg + 4];
        uint32_t a3 = Hs[rloc1 * HSTRIDE + kb + tg + 4];
        const uint32_t* Bk0 = Bs + (kb + tg) * BSTRIDE + nbase;
        const uint32_t* Bk1 = Bs + (kb + tg + 4) * BSTRIDE + nbase;
#pragma unroll
        for (int j = 0; j < 8; j++) {
            uint32_t b0 = Bk0[j * 8 + g];
            uint32_t b1 = Bk1[j * 8 + g];
            mma_tf32(acc[j * 4 + 0], acc[j * 4 + 1], acc[j * 4 + 2], acc[j * 4 + 3],
                     a0, a1, a2, a3, b0, b1);
        }
    }

    if (half == 1)
        split_epi_upper(acc, rloc0, rloc1, tg, bm1, bm2, Ps);
    __syncthreads();
    if (half == 0)
        split_epi_lower(acc, row0, row1, rloc0, rloc1, tg, ba, Ps, hc, dense_out);
}

// ===========================================================================

extern "C" void kernel_launch(void* const* d_in, const int* in_sizes, int n_in,
                              void* d_out, int out_size)
{
    const float* x   = (const float*)d_in[0];
    const int* ei    = (const int*)d_in[1];
    const int* src   = ei;
    const int* dst   = ei + N_EDGES;
    const float* Wc1 = (const float*)d_in[2];  const float* bc1 = (const float*)d_in[3];
    const float* Wc2 = (const float*)d_in[4];  const float* bc2 = (const float*)d_in[5];
    const float* Wc3 = (const float*)d_in[6];  const float* bc3 = (const float*)d_in[7];
    const float* W11 = (const float*)d_in[8];  const float* b11 = (const float*)d_in[9];
    const float* W12 = (const float*)d_in[10]; const float* b12 = (const float*)d_in[11];
    const float* W13 = (const float*)d_in[12]; const float* b13 = (const float*)d_in[13];
    const float* W21 = (const float*)d_in[14]; const float* b21 = (const float*)d_in[15];
    const float* W22 = (const float*)d_in[16]; const float* b22 = (const float*)d_in[17];
    const float* W23 = (const float*)d_in[18]; const float* b23 = (const float*)d_in[19];
    const float* W31 = (const float*)d_in[20]; const float* b31 = (const float*)d_in[21];
    const float* W32 = (const float*)d_in[22]; const float* b32 = (const float*)d_in[23];
    const float* W33 = (const float*)d_in[24]; const float* b33 = (const float*)d_in[25];
    const float* W2  = (const float*)d_in[26]; const float* b2  = (const float*)d_in[27];
    float* out = (float*)d_out;

    __half *hc, *h16;
    float* dense;
    int *deg, *rowstart, *rowend, *rank, *csr;
    cudaGetSymbolAddress((void**)&hc,       g_hc16);
    cudaGetSymbolAddress((void**)&h16,      g_h16);
    cudaGetSymbolAddress((void**)&dense,    g_dense);
    cudaGetSymbolAddress((void**)&deg,      g_deg);
    cudaGetSymbolAddress((void**)&rowstart, g_rowstart);
    cudaGetSymbolAddress((void**)&rowend,   g_rowend);
    cudaGetSymbolAddress((void**)&rank,     g_rank);
    cudaGetSymbolAddress((void**)&csr,      g_csr);

    const int QEDGE_BLOCKS = (N_EDGES / 4 + 255) / 256;
    const int NVEC_BLOCKS  = (N_NODES + 255) / 256;
    const int GATH_BLOCKS  = (N_NODES * 32 + 511) / 512;
    const int MMA_BLOCKS   = (N_NODES + 127) / 128;   // 782

    const int L1_SMEM  = (F_IN * BSTRIDE + 2 * 128 * XSTRIDE) * 4;            // 90112
    const int MID_SMEM = (NOUT * BSTRIDE + 128 * HSTRIDE) * 4
                       + 128 * PSTRIDE * 4;                                   // 53248
    cudaFuncSetAttribute(k_layer1_mma, cudaFuncAttributeMaxDynamicSharedMemorySize,
                         L1_SMEM);
    cudaFuncSetAttribute(k_mid_mma, cudaFuncAttributeMaxDynamicSharedMemorySize,
                         MID_SMEM);

    // Side stream + events (created once; host-side only).
    static cudaStream_t s2 = nullptr;
    static cudaEvent_t evRoot = nullptr, evJoin = nullptr;
    if (s2 == nullptr) {
        cudaStreamCreateWithFlags(&s2, cudaStreamNonBlocking);
        cudaEventCreateWithFlags(&evRoot, cudaEventDisableTiming);
        cudaEventCreateWithFlags(&evJoin, cudaEventDisableTiming);
    }

    // Fork: CSR build on s2, layer-1 GEMM on the main stream.
    cudaEventRecord(evRoot, 0);
    cudaStreamWaitEvent(s2, evRoot, 0);

    k_zero<<<NVEC_BLOCKS, 256, 0, s2>>>(deg);
    k_zero_counter<<<1, 1, 0, s2>>>();
    k_hist<<<QEDGE_BLOCKS, 256, 0, s2>>>(dst, deg, rank);
    k_scanA<<<SCAN_NBLK, SCAN_BLOCK, 0, s2>>>(deg, rowstart, rowend);
    k_fill<<<QEDGE_BLOCKS, 256, 0, s2>>>(src, dst, rowstart, rank, csr);
    cudaEventRecord(evJoin, s2);

    k_layer1_mma<<<MMA_BLOCKS, 512, L1_SMEM>>>(x, Wc1, W11, b11, W12, b12,
                                               W13, b13, hc, dense);

    cudaStreamWaitEvent(0, evJoin, 0);

    // Layer 2: gather (+ layer-1 epilogue -> h1 fp16), then mid GEMM
    k_gather_h<<<GATH_BLOCKS, 512>>>(csr, rowstart, rowend, hc, dense, bc1, h16);
    k_mid_mma<<<MMA_BLOCKS, 512, MID_SMEM>>>(h16, Wc2, W21, b21, W22, b22,
                                             W23, b23, hc, dense);
    // Layer 3
    k_gather_h<<<GATH_BLOCKS, 512>>>(csr, rowstart, rowend, hc, dense, bc2, h16);
    k_mid_mma<<<MMA_BLOCKS, 512, MID_SMEM>>>(h16, Wc3, W31, b31, W32, b32,
                                             W33, b33, hc, dense);
    // Final
    k_gather_final<<<GATH_BLOCKS, 512>>>(csr, rowstart, rowend, hc, dense, bc3,
                                         W2, b2, out);
}